// round 13
// baseline (speedup 1.0000x reference)
#include <cuda_runtime.h>
#include <cstdint>
#include <type_traits>

namespace plp {

constexpr int NBINS = 257;
constexpr int N_CH  = 40;
constexpr int ORDER = 16;
constexpr int RPW   = 32;                     // rows per tile (lane = row)
constexpr int WARP_FLOATS = RPW * NBINS;      // 8224
constexpr int TILE_BYTES  = WARP_FLOATS * 4;  // 32896, multiple of 16
constexpr int NBUF   = 3;                     // shared tile ring (per block)
constexpr int CWARPS = 8;                     // consumer warps per block
constexpr int BLOCK  = CWARPS * 32;
constexpr int BLOCKS_PER_SM = 2;              // 16 warps/SM total

template <int I> using ic = std::integral_constant<int, I>;

// ---------------- compile-time double-precision math ----------------
constexpr double cexp(double x) {
    double s = 1.0, t = 1.0;
    for (int k = 1; k < 60; ++k) { t = t * x / k; s += t; }
    return s;
}
constexpr double cln(double x) {
    int n = 0;
    while (x > 1.3333333333333333) { x *= 0.5; ++n; }
    while (x < 0.75)               { x *= 2.0; --n; }
    double t = (x - 1.0) / (x + 1.0), t2 = t * t, s = 0.0, p = t;
    for (int k = 0; k < 40; ++k) { s += p / (2 * k + 1); p *= t2; }
    return 2.0 * s + n * 0.69314718055994530941723212145818;
}
constexpr double ccos(double x) {
    while (x >  3.14159265358979323846) x -= 6.28318530717958647692528676656;
    while (x < -3.14159265358979323846) x += 6.28318530717958647692528676656;
    double x2 = x * x, s = 1.0, t = 1.0;
    for (int k = 1; k < 30; ++k) { t *= -x2 / ((2.0 * k - 1.0) * (2.0 * k)); s += t; }
    return s;
}
constexpr double csin(double x) {
    double x2 = x * x, s = x, t = x;
    for (int k = 1; k < 30; ++k) { t *= -x2 / ((2.0 * k) * (2.0 * k + 1.0)); s += t; }
    return s;
}

// ---------------- all problem constants, built at compile time ----------------
struct Tables {
    int   chlo[256]; float wlo[256];
    int   chhi[256]; float whi[256];
    float eql[N_CH];
    float Cp[20][ORDER + 1];   // paired cosine coeffs (q=1..20), edges folded into q=1
    float lift[ORDER];
};

constexpr Tables build() {
    Tables T{};
    const double mel_max = 1127.0 * cln(1.0 + 8000.0 / 700.0);
    const double d = mel_max / 41.0;
    double cf[41]{};   for (int s = 0; s < 41; ++s) cf[s] = d * (s + 1);
    double diff[41]{}; diff[0] = cf[0];
    for (int i = 1; i < 41; ++i) diff[i] = cf[i] - cf[i - 1];

    for (int b = 1; b < 256; ++b) {
        const double mel = 1127.0 * cln(1.0 + (31.25 * b) / 700.0);
        int ch = 0;
        for (int s = 0; s < 41; ++s) if (cf[s] < mel) ++ch;   // searchsorted 'left'
        const double w = (cf[ch] - mel) / diff[ch];
        T.chlo[b] = ch - 1;                 T.wlo[b] = (float)w;
        T.chhi[b] = (ch <= 39) ? ch : -1;   T.whi[b] = (float)(1.0 - w);
    }
    T.chlo[0] = -1; T.chhi[0] = -1;
    for (int c = 0; c < N_CH; ++c) {
        const double fhz = 700.0 * (cexp(cf[c] / 1127.0) - 1.0);
        const double f2  = fhz * fhz;
        T.eql[c] = (float)((f2 / (f2 + 160000.0)) * (f2 / (f2 + 160000.0))
                           * (f2 + 1440000.0) / (f2 + 9610000.0));
    }
    for (int q = 1; q <= 20; ++q)
        for (int k = 0; k <= ORDER; ++k) {
            double v = 2.0 * ccos(6.28318530717958647692528676656
                                  * (double)(q * k) / 82.0) / 82.0;
            if (q == 1) v += 1.0 / 82.0;
            T.Cp[q - 1][k] = (float)v;
        }
    for (int m = 1; m <= ORDER; ++m)
        T.lift[m - 1] = (float)(1.0 + 11.0 * csin(3.14159265358979323846 * m / 22.0));
    return T;
}
constexpr Tables TB = build();

// ---------------- compile-time for-loop ----------------
template <int I, int N> struct SF {
    template <class F>
    __device__ __forceinline__ static void run(F&& f) {
        f(ic<I>{});
        SF<I + 1, N>::run((F&&)f);
    }
};
template <int N> struct SF<N, N> {
    template <class F> __device__ __forceinline__ static void run(F&&) {}
};

__device__ __forceinline__ void mbar_init(unsigned bar, unsigned cnt) {
    asm volatile("mbarrier.init.shared.b64 [%0], %1;" :: "r"(bar), "r"(cnt) : "memory");
}
__device__ __forceinline__ void fence_async_shared() {
    asm volatile("fence.proxy.async.shared::cta;" ::: "memory");
}
__device__ __forceinline__ void mbar_expect_tx(unsigned bar, unsigned bytes) {
    asm volatile("mbarrier.arrive.expect_tx.shared.b64 _, [%0], %1;"
                 :: "r"(bar), "r"(bytes) : "memory");
}
__device__ __forceinline__ void bulk_g2s(unsigned dst, const void* src,
                                         unsigned bytes, unsigned bar) {
    asm volatile(
        "cp.async.bulk.shared::cta.global.mbarrier::complete_tx::bytes "
        "[%0], [%1], %2, [%3];"
        :: "r"(dst), "l"(src), "r"(bytes), "r"(bar) : "memory");
}
__device__ __forceinline__ void mbar_wait(unsigned bar, unsigned parity) {
    asm volatile(
        "{\n\t"
        ".reg .pred P;\n"
        "WAIT_%=:\n\t"
        "mbarrier.try_wait.parity.acquire.cta.shared::cta.b64 P, [%0], %1, 0x989680;\n\t"
        "@P bra.uni DONE_%=;\n\t"
        "bra.uni WAIT_%=;\n"
        "DONE_%=:\n\t"
        "}"
        :: "r"(bar), "r"(parity) : "memory");
}

__global__ void __launch_bounds__(BLOCK, BLOCKS_PER_SM)
plp_kernel(const float* __restrict__ x, float* __restrict__ out, int nTiles) {
    extern __shared__ __align__(128) float xs[];           // NBUF * 8224 floats
    __shared__ __align__(8) unsigned long long fullb[NBUF];
    __shared__ unsigned eflag[NBUF];                       // completed-use counters

    const int lane = threadIdx.x & 31;
    const int w    = threadIdx.x >> 5;

    const unsigned sfull = (unsigned)__cvta_generic_to_shared(&fullb[0]);
    const unsigned sbase = (unsigned)__cvta_generic_to_shared(xs);
    volatile unsigned* ef = (volatile unsigned*)eflag;

    if (threadIdx.x == 0) {
        #pragma unroll
        for (int i = 0; i < NBUF; ++i) {
            mbar_init(sfull + 8u * i, 1);
            eflag[i] = 0u;
        }
        fence_async_shared();
    }
    __syncthreads();

    // fill helper: called by lane 0 only. Waits until all prior uses of the
    // buffer are consumed, then arms the barrier and launches the TMA.
    auto issue_fill = [&](int idx, long long tile) {
        const int b = idx % NBUF;
        const unsigned n = (unsigned)(idx / NBUF);
        while (ef[b] < n) { __nanosleep(64); }   // acquire-spin (fenced below)
        __threadfence_block();
        fence_async_shared();
        mbar_expect_tx(sfull + 8u * b, TILE_BYTES);
        bulk_g2s(sbase + (unsigned)(b * TILE_BYTES),
                 x + tile * WARP_FLOATS, TILE_BYTES, sfull + 8u * b);
    };

    // prologue: each warp arms its first tile (warps > NBUF-1 sleep-spin until
    // earlier uses of their buffer are consumed; the idx DAG guarantees progress)
    {
        const long long t0 = blockIdx.x + (long long)gridDim.x * w;
        if (lane == 0 && t0 < nTiles) issue_fill(w, t0);
    }
    __syncwarp();

    for (int k = 0;; ++k) {
        const int idx = w + CWARPS * k;
        const long long tile = blockIdx.x + (long long)gridDim.x * idx;
        if (tile >= nTiles) break;
        const int buf = idx % NBUF;
        const unsigned n = (unsigned)(idx / NBUF);

        // PARITY-SAFE wait: only lane 0 (which armed this phase) waits on the
        // mbarrier; __syncwarp blocks lanes 1..31 and publishes the TMA writes.
        if (lane == 0) mbar_wait(sfull + 8u * buf, n & 1u);
        __syncwarp();

        // ---- lane owns one row; stride 257 (odd) => bank-conflict-free ----
        const float* xr = xs + buf * WARP_FLOATS + lane * NBINS;

        float fb[N_CH];
        SF<0, N_CH>::run([&](auto c) { fb[c.value] = 0.f; });

        SF<1, 256>::run([&](auto bc) {
            constexpr int bb = bc.value;
            constexpr int clo = TB.chlo[bb];
            constexpr int chi = TB.chhi[bb];
            if constexpr (clo >= 0 || chi >= 0) {
                const float xv = xr[bb];
                if constexpr (clo >= 0) { constexpr float wt = TB.wlo[bb]; fb[clo] = fmaf(wt, xv, fb[clo]); }
                if constexpr (chi >= 0) { constexpr float wt = TB.whi[bb]; fb[chi] = fmaf(wt, xv, fb[chi]); }
            }
        });

        // release buffer (all lanes done reading), then arm NEXT tile's fill
        // BEFORE the epilogue so the TMA flies under the epilogue compute.
        __syncwarp();
        if (lane == 0) {
            __threadfence_block();
            ef[buf] = n + 1u;                       // release
            const int idx2 = idx + CWARPS;
            const long long tile2 = blockIdx.x + (long long)gridDim.x * idx2;
            if (tile2 < nTiles) issue_fill(idx2, tile2);
        }

        // ---- equal-loudness + compression (MUFU) ----
        float y[N_CH];
        SF<0, N_CH>::run([&](auto cc_) {
            constexpr int c = cc_.value;
            constexpr float e = TB.eql[c];
            const float v = fmaxf(fb[c], 1e-5f) * e;
            y[c] = __expf(0.33f * __logf(v));
        });

        // ---- autocorrelation via parity-folded cosine transform ----
        float sp[20], sm[20];
        SF<0, 20>::run([&](auto qc) {
            constexpr int q = qc.value;
            sp[q] = y[q] + y[39 - q];
            sm[q] = y[q] - y[39 - q];
        });
        float r[ORDER + 1];
        SF<0, ORDER + 1>::run([&](auto kc) { r[kc.value] = 0.f; });
        SF<0, 20>::run([&](auto qc) {
            constexpr int q = qc.value;
            const float vp = sp[q], vm = sm[q];
            SF<0, ORDER + 1>::run([&](auto kc) {
                constexpr int kk2 = kc.value;
                constexpr float cqk = TB.Cp[q][kk2];
                r[kk2] = fmaf(cqk, (kk2 & 1) ? vm : vp, r[kk2]);
            });
        });

        // ---- Levinson-Durbin (order 16) ----
        float A[ORDER];
        float E = r[0];
        #pragma unroll
        for (int ii = 1; ii <= ORDER; ++ii) {
            float acc = r[ii];
            #pragma unroll
            for (int j = 1; j < ii; ++j) acc += A[j - 1] * r[ii - j];
            const float kk = -__fdividef(acc, E);
            #pragma unroll
            for (int j = 0; j < (ii - 1) / 2; ++j) {
                const float tt = A[j];
                A[j]          = tt + kk * A[ii - 2 - j];
                A[ii - 2 - j] = A[ii - 2 - j] + kk * tt;
            }
            if (((ii - 1) & 1) == 1) {
                const int mid = (ii - 2) / 2;
                A[mid] = A[mid] + kk * A[mid];
            }
            A[ii - 1] = kk;
            E = E * (1.0f - kk * kk);
        }

        // ---- LPC -> cepstrum ----
        float cst[ORDER + 1];
        cst[0] = 0.5f * __logf(E);
        #pragma unroll
        for (int m = 1; m <= ORDER; ++m) {
            float acc = A[m - 1];
            #pragma unroll
            for (int k2 = 1; k2 < m; ++k2) {
                const float ratio = (float)k2 / (float)m;
                acc += ratio * cst[k2] * A[m - k2 - 1];
            }
            cst[m] = -acc;
        }

        // ---- lifter + store (warp writes 2KB contiguous) ----
        float o[ORDER];
        SF<0, ORDER>::run([&](auto icx) {
            constexpr int ii = icx.value;
            constexpr float lf = TB.lift[ii];
            o[ii] = cst[ii + 1] * lf;
        });

        const long long row = tile * RPW + lane;
        float4* o4 = reinterpret_cast<float4*>(out + row * 16);
        o4[0] = make_float4(o[0],  o[1],  o[2],  o[3]);
        o4[1] = make_float4(o[4],  o[5],  o[6],  o[7]);
        o4[2] = make_float4(o[8],  o[9],  o[10], o[11]);
        o4[3] = make_float4(o[12], o[13], o[14], o[15]);
    }
}

} // namespace plp

extern "C" void kernel_launch(void* const* d_in, const int* in_sizes, int n_in,
                              void* d_out, int out_size) {
    const float* x = (const float*)d_in[0];
    float* out = (float*)d_out;

    const int rows   = in_sizes[0] / plp::NBINS;   // 131072
    const int nTiles = rows / plp::RPW;            // 4096

    const int smem = plp::NBUF * plp::TILE_BYTES;  // 98688 B
    cudaFuncSetAttribute(plp::plp_kernel,
                         cudaFuncAttributeMaxDynamicSharedMemorySize, smem);
    int nSM = 0, dev = 0;
    cudaGetDevice(&dev);
    cudaDeviceGetAttribute(&nSM, cudaDevAttrMultiProcessorCount, dev);
    if (nSM <= 0) nSM = 148;

    int grid = plp::BLOCKS_PER_SM * nSM;           // 2 persistent blocks per SM
    if (grid > nTiles) grid = nTiles;

    plp::plp_kernel<<<grid, plp::BLOCK, smem>>>(x, out, nTiles);
}

// round 14
// speedup vs baseline: 1.5603x; 1.5603x over previous
#include <cuda_runtime.h>
#include <cstdint>
#include <type_traits>

namespace plp {

constexpr int NBINS = 257;
constexpr int N_CH  = 40;
constexpr int ORDER = 16;
constexpr int RPW   = 32;                     // rows per tile (lane = row)
constexpr int WARP_FLOATS = RPW * NBINS;      // 8224
constexpr int TILE_BYTES  = WARP_FLOATS * 4;  // 32896, multiple of 16
constexpr int NBUF   = 6;                     // tile ring (197 KB smem)
constexpr int CWARPS = 8;                     // consumer warps
constexpr int BLOCK  = (CWARPS + 1) * 32;     // + 1 producer warp

template <int I> using ic = std::integral_constant<int, I>;

// ---------------- compile-time double-precision math ----------------
constexpr double cexp(double x) {
    double s = 1.0, t = 1.0;
    for (int k = 1; k < 60; ++k) { t = t * x / k; s += t; }
    return s;
}
constexpr double cln(double x) {
    int n = 0;
    while (x > 1.3333333333333333) { x *= 0.5; ++n; }
    while (x < 0.75)               { x *= 2.0; --n; }
    double t = (x - 1.0) / (x + 1.0), t2 = t * t, s = 0.0, p = t;
    for (int k = 0; k < 40; ++k) { s += p / (2 * k + 1); p *= t2; }
    return 2.0 * s + n * 0.69314718055994530941723212145818;
}
constexpr double ccos(double x) {
    while (x >  3.14159265358979323846) x -= 6.28318530717958647692528676656;
    while (x < -3.14159265358979323846) x += 6.28318530717958647692528676656;
    double x2 = x * x, s = 1.0, t = 1.0;
    for (int k = 1; k < 30; ++k) { t *= -x2 / ((2.0 * k - 1.0) * (2.0 * k)); s += t; }
    return s;
}
constexpr double csin(double x) {
    double x2 = x * x, s = x, t = x;
    for (int k = 1; k < 30; ++k) { t *= -x2 / ((2.0 * k) * (2.0 * k + 1.0)); s += t; }
    return s;
}

// ---------------- all problem constants, built at compile time ----------------
struct Tables {
    int   chlo[256]; float wlo[256];
    int   chhi[256]; float whi[256];
    float eql[N_CH];
    float Cp[20][ORDER + 1];   // paired cosine coeffs (q=1..20), edges folded into q=1
    float lift[ORDER];
};

constexpr Tables build() {
    Tables T{};
    const double mel_max = 1127.0 * cln(1.0 + 8000.0 / 700.0);
    const double d = mel_max / 41.0;
    double cf[41]{};   for (int s = 0; s < 41; ++s) cf[s] = d * (s + 1);
    double diff[41]{}; diff[0] = cf[0];
    for (int i = 1; i < 41; ++i) diff[i] = cf[i] - cf[i - 1];

    for (int b = 1; b < 256; ++b) {
        const double mel = 1127.0 * cln(1.0 + (31.25 * b) / 700.0);
        int ch = 0;
        for (int s = 0; s < 41; ++s) if (cf[s] < mel) ++ch;   // searchsorted 'left'
        const double w = (cf[ch] - mel) / diff[ch];
        T.chlo[b] = ch - 1;                 T.wlo[b] = (float)w;
        T.chhi[b] = (ch <= 39) ? ch : -1;   T.whi[b] = (float)(1.0 - w);
    }
    T.chlo[0] = -1; T.chhi[0] = -1;
    for (int c = 0; c < N_CH; ++c) {
        const double fhz = 700.0 * (cexp(cf[c] / 1127.0) - 1.0);
        const double f2  = fhz * fhz;
        T.eql[c] = (float)((f2 / (f2 + 160000.0)) * (f2 / (f2 + 160000.0))
                           * (f2 + 1440000.0) / (f2 + 9610000.0));
    }
    for (int q = 1; q <= 20; ++q)
        for (int k = 0; k <= ORDER; ++k) {
            double v = 2.0 * ccos(6.28318530717958647692528676656
                                  * (double)(q * k) / 82.0) / 82.0;
            if (q == 1) v += 1.0 / 82.0;
            T.Cp[q - 1][k] = (float)v;
        }
    for (int m = 1; m <= ORDER; ++m)
        T.lift[m - 1] = (float)(1.0 + 11.0 * csin(3.14159265358979323846 * m / 22.0));
    return T;
}
constexpr Tables TB = build();

// ---------------- compile-time for-loop ----------------
template <int I, int N> struct SF {
    template <class F>
    __device__ __forceinline__ static void run(F&& f) {
        f(ic<I>{});
        SF<I + 1, N>::run((F&&)f);
    }
};
template <int N> struct SF<N, N> {
    template <class F> __device__ __forceinline__ static void run(F&&) {}
};

__device__ __forceinline__ void mbar_init(unsigned bar, unsigned cnt) {
    asm volatile("mbarrier.init.shared.b64 [%0], %1;" :: "r"(bar), "r"(cnt) : "memory");
}
__device__ __forceinline__ void fence_async_shared() {
    asm volatile("fence.proxy.async.shared::cta;" ::: "memory");
}
__device__ __forceinline__ void mbar_expect_tx(unsigned bar, unsigned bytes) {
    asm volatile("mbarrier.arrive.expect_tx.shared.b64 _, [%0], %1;"
                 :: "r"(bar), "r"(bytes) : "memory");
}
__device__ __forceinline__ void bulk_g2s(unsigned dst, const void* src,
                                         unsigned bytes, unsigned bar) {
    asm volatile(
        "cp.async.bulk.shared::cta.global.mbarrier::complete_tx::bytes "
        "[%0], [%1], %2, [%3];"
        :: "r"(dst), "l"(src), "r"(bytes), "r"(bar) : "memory");
}
__device__ __forceinline__ void mbar_wait(unsigned bar, unsigned parity) {
    asm volatile(
        "{\n\t"
        ".reg .pred P;\n"
        "WAIT_%=:\n\t"
        "mbarrier.try_wait.parity.acquire.cta.shared::cta.b64 P, [%0], %1, 0x989680;\n\t"
        "@P bra.uni DONE_%=;\n\t"
        "bra.uni WAIT_%=;\n"
        "DONE_%=:\n\t"
        "}"
        :: "r"(bar), "r"(parity) : "memory");
}

__global__ void __launch_bounds__(BLOCK, 1)
plp_kernel(const float* __restrict__ x, float* __restrict__ out, int nTiles) {
    extern __shared__ __align__(128) float xs[];           // NBUF * 8224 floats
    __shared__ __align__(8) unsigned long long fullb[NBUF];
    __shared__ unsigned ff[NBUF];   // fills published  (count per buffer)
    __shared__ unsigned ef[NBUF];   // consumes done    (count per buffer)

    const int lane = threadIdx.x & 31;
    const int w    = threadIdx.x >> 5;

    const unsigned sfull = (unsigned)__cvta_generic_to_shared(&fullb[0]);
    const unsigned sbase = (unsigned)__cvta_generic_to_shared(xs);
    volatile unsigned* vff = (volatile unsigned*)ff;
    volatile unsigned* vef = (volatile unsigned*)ef;

    if (threadIdx.x == 0) {
        #pragma unroll
        for (int i = 0; i < NBUF; ++i) {
            mbar_init(sfull + 8u * i, 1);
            ff[i] = 0u; ef[i] = 0u;
        }
        fence_async_shared();
    }
    __syncthreads();

    // tiles owned by this block: tile(idx) = blockIdx + gridDim * idx
    const int myTiles = (blockIdx.x < nTiles)
                      ? ((nTiles - 1 - (int)blockIdx.x) / (int)gridDim.x + 1) : 0;

    if (w == CWARPS) {
        // ================= PRODUCER WARP (lane 0) =================
        if (lane == 0) {
            int head = 0;
            for (int tail = 0; tail < myTiles; ++tail) {
                // issue fills up to NBUF deep (always at least tile 'tail')
                while (head < myTiles && head < tail + NBUF) {
                    const int b = head % NBUF;
                    const unsigned n = (unsigned)(head / NBUF);
                    if (vef[b] < n) {
                        if (head > tail) break;                 // optional depth
                        while (vef[b] < n) __nanosleep(128);    // mandatory
                    }
                    __threadfence_block();
                    fence_async_shared();                       // reads before async writes
                    mbar_expect_tx(sfull + 8u * b, TILE_BYTES);
                    const long long tile = blockIdx.x + (long long)gridDim.x * head;
                    bulk_g2s(sbase + (unsigned)(b * TILE_BYTES),
                             x + tile * WARP_FLOATS, TILE_BYTES, sfull + 8u * b);
                    ++head;
                }
                // retire tile 'tail': wait its completion (armed by this thread
                // => phase skew <=1, parity sound), then publish.
                mbar_wait(sfull + 8u * (tail % NBUF), (unsigned)((tail / NBUF) & 1));
                __threadfence_block();
                vff[tail % NBUF] = (unsigned)(tail / NBUF) + 1u;
            }
        }
        return;   // producer warp done (consumers hold the block alive)
    }

    // ================= CONSUMER WARPS =================
    for (int k = 0;; ++k) {
        const int idx = w + CWARPS * k;
        if (idx >= myTiles) break;
        const long long tile = blockIdx.x + (long long)gridDim.x * idx;
        const int buf = idx % NBUF;
        const unsigned n = (unsigned)(idx / NBUF);

        // wait ONLY for own data (all lanes spin on the published counter)
        while (vff[buf] < n + 1u) __nanosleep(64);
        __threadfence_block();

        // ---- lane owns one row; stride 257 (odd) => bank-conflict-free ----
        const float* xr = xs + buf * WARP_FLOATS + lane * NBINS;

        float fb[N_CH];
        SF<0, N_CH>::run([&](auto c) { fb[c.value] = 0.f; });

        SF<1, 256>::run([&](auto bc) {
            constexpr int bb = bc.value;
            constexpr int clo = TB.chlo[bb];
            constexpr int chi = TB.chhi[bb];
            if constexpr (clo >= 0 || chi >= 0) {
                const float xv = xr[bb];
                if constexpr (clo >= 0) { constexpr float wt = TB.wlo[bb]; fb[clo] = fmaf(wt, xv, fb[clo]); }
                if constexpr (chi >= 0) { constexpr float wt = TB.whi[bb]; fb[chi] = fmaf(wt, xv, fb[chi]); }
            }
        });

        // release buffer — consumers have no further waits this tile
        __syncwarp();
        if (lane == 0) {
            __threadfence_block();
            vef[buf] = n + 1u;
        }

        // ---- equal-loudness + compression (MUFU) ----
        float y[N_CH];
        SF<0, N_CH>::run([&](auto cc_) {
            constexpr int c = cc_.value;
            constexpr float e = TB.eql[c];
            const float v = fmaxf(fb[c], 1e-5f) * e;
            y[c] = __expf(0.33f * __logf(v));
        });

        // ---- autocorrelation via parity-folded cosine transform ----
        float sp[20], sm[20];
        SF<0, 20>::run([&](auto qc) {
            constexpr int q = qc.value;
            sp[q] = y[q] + y[39 - q];
            sm[q] = y[q] - y[39 - q];
        });
        float r[ORDER + 1];
        SF<0, ORDER + 1>::run([&](auto kc) { r[kc.value] = 0.f; });
        SF<0, 20>::run([&](auto qc) {
            constexpr int q = qc.value;
            const float vp = sp[q], vm = sm[q];
            SF<0, ORDER + 1>::run([&](auto kc) {
                constexpr int kk2 = kc.value;
                constexpr float cqk = TB.Cp[q][kk2];
                r[kk2] = fmaf(cqk, (kk2 & 1) ? vm : vp, r[kk2]);
            });
        });

        // ---- Levinson-Durbin (order 16) ----
        float A[ORDER];
        float E = r[0];
        #pragma unroll
        for (int ii = 1; ii <= ORDER; ++ii) {
            float acc = r[ii];
            #pragma unroll
            for (int j = 1; j < ii; ++j) acc += A[j - 1] * r[ii - j];
            const float kk = -__fdividef(acc, E);
            #pragma unroll
            for (int j = 0; j < (ii - 1) / 2; ++j) {
                const float tt = A[j];
                A[j]          = tt + kk * A[ii - 2 - j];
                A[ii - 2 - j] = A[ii - 2 - j] + kk * tt;
            }
            if (((ii - 1) & 1) == 1) {
                const int mid = (ii - 2) / 2;
                A[mid] = A[mid] + kk * A[mid];
            }
            A[ii - 1] = kk;
            E = E * (1.0f - kk * kk);
        }

        // ---- LPC -> cepstrum ----
        float cst[ORDER + 1];
        cst[0] = 0.5f * __logf(E);
        #pragma unroll
        for (int m = 1; m <= ORDER; ++m) {
            float acc = A[m - 1];
            #pragma unroll
            for (int k2 = 1; k2 < m; ++k2) {
                const float ratio = (float)k2 / (float)m;
                acc += ratio * cst[k2] * A[m - k2 - 1];
            }
            cst[m] = -acc;
        }

        // ---- lifter + store (warp writes 2KB contiguous) ----
        float o[ORDER];
        SF<0, ORDER>::run([&](auto icx) {
            constexpr int ii = icx.value;
            constexpr float lf = TB.lift[ii];
            o[ii] = cst[ii + 1] * lf;
        });

        const long long row = tile * RPW + lane;
        float4* o4 = reinterpret_cast<float4*>(out + row * 16);
        o4[0] = make_float4(o[0],  o[1],  o[2],  o[3]);
        o4[1] = make_float4(o[4],  o[5],  o[6],  o[7]);
        o4[2] = make_float4(o[8],  o[9],  o[10], o[11]);
        o4[3] = make_float4(o[12], o[13], o[14], o[15]);
    }
}

} // namespace plp

extern "C" void kernel_launch(void* const* d_in, const int* in_sizes, int n_in,
                              void* d_out, int out_size) {
    const float* x = (const float*)d_in[0];
    float* out = (float*)d_out;

    const int rows   = in_sizes[0] / plp::NBINS;   // 131072
    const int nTiles = rows / plp::RPW;            // 4096

    const int smem = plp::NBUF * plp::TILE_BYTES;  // 197376 B
    cudaFuncSetAttribute(plp::plp_kernel,
                         cudaFuncAttributeMaxDynamicSharedMemorySize, smem);
    int nSM = 0, dev = 0;
    cudaGetDevice(&dev);
    cudaDeviceGetAttribute(&nSM, cudaDevAttrMultiProcessorCount, dev);
    if (nSM <= 0) nSM = 148;

    int grid = nSM;                                // 1 persistent block per SM
    if (grid > nTiles) grid = nTiles;

    plp::plp_kernel<<<grid, plp::BLOCK, smem>>>(x, out, nTiles);
}

// round 15
// speedup vs baseline: 1.5620x; 1.0011x over previous
#include <cuda_runtime.h>
#include <cstdint>
#include <type_traits>

namespace plp {

constexpr int NBINS = 257;
constexpr int N_CH  = 40;
constexpr int ORDER = 16;
constexpr int RPW   = 32;                     // rows per tile (lane = row)
constexpr int WARP_FLOATS = RPW * NBINS;      // 8224
constexpr int TILE_BYTES  = WARP_FLOATS * 4;  // 32896, multiple of 16
constexpr int NBUF   = 3;                     // tile ring per block
constexpr int CWARPS = 4;                     // consumer warps per block
constexpr int BLOCK  = (CWARPS + 1) * 32;     // 160: + 1 producer warp
constexpr int BLOCKS_PER_SM = 2;              // 2 independent rings per SM

template <int I> using ic = std::integral_constant<int, I>;

// ---------------- compile-time double-precision math ----------------
constexpr double cexp(double x) {
    double s = 1.0, t = 1.0;
    for (int k = 1; k < 60; ++k) { t = t * x / k; s += t; }
    return s;
}
constexpr double cln(double x) {
    int n = 0;
    while (x > 1.3333333333333333) { x *= 0.5; ++n; }
    while (x < 0.75)               { x *= 2.0; --n; }
    double t = (x - 1.0) / (x + 1.0), t2 = t * t, s = 0.0, p = t;
    for (int k = 0; k < 40; ++k) { s += p / (2 * k + 1); p *= t2; }
    return 2.0 * s + n * 0.69314718055994530941723212145818;
}
constexpr double ccos(double x) {
    while (x >  3.14159265358979323846) x -= 6.28318530717958647692528676656;
    while (x < -3.14159265358979323846) x += 6.28318530717958647692528676656;
    double x2 = x * x, s = 1.0, t = 1.0;
    for (int k = 1; k < 30; ++k) { t *= -x2 / ((2.0 * k - 1.0) * (2.0 * k)); s += t; }
    return s;
}
constexpr double csin(double x) {
    double x2 = x * x, s = x, t = x;
    for (int k = 1; k < 30; ++k) { t *= -x2 / ((2.0 * k) * (2.0 * k + 1.0)); s += t; }
    return s;
}

// ---------------- all problem constants, built at compile time ----------------
struct Tables {
    int   chlo[256]; float wlo[256];
    int   chhi[256]; float whi[256];
    float eql[N_CH];
    float Cp[20][ORDER + 1];   // paired cosine coeffs (q=1..20), edges folded into q=1
    float lift[ORDER];
};

constexpr Tables build() {
    Tables T{};
    const double mel_max = 1127.0 * cln(1.0 + 8000.0 / 700.0);
    const double d = mel_max / 41.0;
    double cf[41]{};   for (int s = 0; s < 41; ++s) cf[s] = d * (s + 1);
    double diff[41]{}; diff[0] = cf[0];
    for (int i = 1; i < 41; ++i) diff[i] = cf[i] - cf[i - 1];

    for (int b = 1; b < 256; ++b) {
        const double mel = 1127.0 * cln(1.0 + (31.25 * b) / 700.0);
        int ch = 0;
        for (int s = 0; s < 41; ++s) if (cf[s] < mel) ++ch;   // searchsorted 'left'
        const double w = (cf[ch] - mel) / diff[ch];
        T.chlo[b] = ch - 1;                 T.wlo[b] = (float)w;
        T.chhi[b] = (ch <= 39) ? ch : -1;   T.whi[b] = (float)(1.0 - w);
    }
    T.chlo[0] = -1; T.chhi[0] = -1;
    for (int c = 0; c < N_CH; ++c) {
        const double fhz = 700.0 * (cexp(cf[c] / 1127.0) - 1.0);
        const double f2  = fhz * fhz;
        T.eql[c] = (float)((f2 / (f2 + 160000.0)) * (f2 / (f2 + 160000.0))
                           * (f2 + 1440000.0) / (f2 + 9610000.0));
    }
    for (int q = 1; q <= 20; ++q)
        for (int k = 0; k <= ORDER; ++k) {
            double v = 2.0 * ccos(6.28318530717958647692528676656
                                  * (double)(q * k) / 82.0) / 82.0;
            if (q == 1) v += 1.0 / 82.0;
            T.Cp[q - 1][k] = (float)v;
        }
    for (int m = 1; m <= ORDER; ++m)
        T.lift[m - 1] = (float)(1.0 + 11.0 * csin(3.14159265358979323846 * m / 22.0));
    return T;
}
constexpr Tables TB = build();

// ---------------- compile-time for-loop ----------------
template <int I, int N> struct SF {
    template <class F>
    __device__ __forceinline__ static void run(F&& f) {
        f(ic<I>{});
        SF<I + 1, N>::run((F&&)f);
    }
};
template <int N> struct SF<N, N> {
    template <class F> __device__ __forceinline__ static void run(F&&) {}
};

__device__ __forceinline__ void mbar_init(unsigned bar, unsigned cnt) {
    asm volatile("mbarrier.init.shared.b64 [%0], %1;" :: "r"(bar), "r"(cnt) : "memory");
}
__device__ __forceinline__ void fence_async_shared() {
    asm volatile("fence.proxy.async.shared::cta;" ::: "memory");
}
__device__ __forceinline__ void mbar_expect_tx(unsigned bar, unsigned bytes) {
    asm volatile("mbarrier.arrive.expect_tx.shared.b64 _, [%0], %1;"
                 :: "r"(bar), "r"(bytes) : "memory");
}
__device__ __forceinline__ void bulk_g2s(unsigned dst, const void* src,
                                         unsigned bytes, unsigned bar) {
    asm volatile(
        "cp.async.bulk.shared::cta.global.mbarrier::complete_tx::bytes "
        "[%0], [%1], %2, [%3];"
        :: "r"(dst), "l"(src), "r"(bytes), "r"(bar) : "memory");
}
__device__ __forceinline__ void mbar_wait(unsigned bar, unsigned parity) {
    asm volatile(
        "{\n\t"
        ".reg .pred P;\n"
        "WAIT_%=:\n\t"
        "mbarrier.try_wait.parity.acquire.cta.shared::cta.b64 P, [%0], %1, 0x989680;\n\t"
        "@P bra.uni DONE_%=;\n\t"
        "bra.uni WAIT_%=;\n"
        "DONE_%=:\n\t"
        "}"
        :: "r"(bar), "r"(parity) : "memory");
}

__global__ void __launch_bounds__(BLOCK, BLOCKS_PER_SM)
plp_kernel(const float* __restrict__ x, float* __restrict__ out, int nTiles) {
    extern __shared__ __align__(128) float xs[];           // NBUF * 8224 floats
    __shared__ __align__(8) unsigned long long fullb[NBUF];
    __shared__ unsigned ff[NBUF];   // fills published  (count per buffer)
    __shared__ unsigned ef[NBUF];   // consumes done    (count per buffer)

    const int lane = threadIdx.x & 31;
    const int w    = threadIdx.x >> 5;

    const unsigned sfull = (unsigned)__cvta_generic_to_shared(&fullb[0]);
    const unsigned sbase = (unsigned)__cvta_generic_to_shared(xs);
    volatile unsigned* vff = (volatile unsigned*)ff;
    volatile unsigned* vef = (volatile unsigned*)ef;

    if (threadIdx.x == 0) {
        #pragma unroll
        for (int i = 0; i < NBUF; ++i) {
            mbar_init(sfull + 8u * i, 1);
            ff[i] = 0u; ef[i] = 0u;
        }
        fence_async_shared();
    }
    __syncthreads();

    // tiles owned by this block: tile(idx) = blockIdx + gridDim * idx
    const int myTiles = (blockIdx.x < nTiles)
                      ? ((nTiles - 1 - (int)blockIdx.x) / (int)gridDim.x + 1) : 0;

    if (w == CWARPS) {
        // ================= PRODUCER WARP (lane 0) =================
        if (lane == 0) {
            int head = 0;
            for (int tail = 0; tail < myTiles; ++tail) {
                // issue fills up to NBUF deep (always at least tile 'tail')
                while (head < myTiles && head < tail + NBUF) {
                    const int b = head % NBUF;
                    const unsigned n = (unsigned)(head / NBUF);
                    if (vef[b] < n) {
                        if (head > tail) break;                 // optional depth
                        while (vef[b] < n) __nanosleep(128);    // mandatory
                    }
                    __threadfence_block();
                    fence_async_shared();                       // reads before async writes
                    mbar_expect_tx(sfull + 8u * b, TILE_BYTES);
                    const long long tile = blockIdx.x + (long long)gridDim.x * head;
                    bulk_g2s(sbase + (unsigned)(b * TILE_BYTES),
                             x + tile * WARP_FLOATS, TILE_BYTES, sfull + 8u * b);
                    ++head;
                }
                // retire tile 'tail': wait its completion (armed by this thread
                // => phase skew <=1, parity sound), then publish.
                mbar_wait(sfull + 8u * (tail % NBUF), (unsigned)((tail / NBUF) & 1));
                __threadfence_block();
                vff[tail % NBUF] = (unsigned)(tail / NBUF) + 1u;
            }
        }
        return;   // producer warp done (consumers hold the block alive)
    }

    // ================= CONSUMER WARPS =================
    for (int k = 0;; ++k) {
        const int idx = w + CWARPS * k;
        if (idx >= myTiles) break;
        const long long tile = blockIdx.x + (long long)gridDim.x * idx;
        const int buf = idx % NBUF;
        const unsigned n = (unsigned)(idx / NBUF);

        // wait ONLY for own data (all lanes spin on the published counter)
        while (vff[buf] < n + 1u) __nanosleep(64);
        __threadfence_block();

        // ---- lane owns one row; stride 257 (odd) => bank-conflict-free ----
        const float* xr = xs + buf * WARP_FLOATS + lane * NBINS;

        float fb[N_CH];
        SF<0, N_CH>::run([&](auto c) { fb[c.value] = 0.f; });

        SF<1, 256>::run([&](auto bc) {
            constexpr int bb = bc.value;
            constexpr int clo = TB.chlo[bb];
            constexpr int chi = TB.chhi[bb];
            if constexpr (clo >= 0 || chi >= 0) {
                const float xv = xr[bb];
                if constexpr (clo >= 0) { constexpr float wt = TB.wlo[bb]; fb[clo] = fmaf(wt, xv, fb[clo]); }
                if constexpr (chi >= 0) { constexpr float wt = TB.whi[bb]; fb[chi] = fmaf(wt, xv, fb[chi]); }
            }
        });

        // release buffer — consumers have no further waits this tile
        __syncwarp();
        if (lane == 0) {
            __threadfence_block();
            vef[buf] = n + 1u;
        }

        // ---- equal-loudness + compression (MUFU) ----
        float y[N_CH];
        SF<0, N_CH>::run([&](auto cc_) {
            constexpr int c = cc_.value;
            constexpr float e = TB.eql[c];
            const float v = fmaxf(fb[c], 1e-5f) * e;
            y[c] = __expf(0.33f * __logf(v));
        });

        // ---- autocorrelation via parity-folded cosine transform ----
        float sp[20], sm[20];
        SF<0, 20>::run([&](auto qc) {
            constexpr int q = qc.value;
            sp[q] = y[q] + y[39 - q];
            sm[q] = y[q] - y[39 - q];
        });
        float r[ORDER + 1];
        SF<0, ORDER + 1>::run([&](auto kc) { r[kc.value] = 0.f; });
        SF<0, 20>::run([&](auto qc) {
            constexpr int q = qc.value;
            const float vp = sp[q], vm = sm[q];
            SF<0, ORDER + 1>::run([&](auto kc) {
                constexpr int kk2 = kc.value;
                constexpr float cqk = TB.Cp[q][kk2];
                r[kk2] = fmaf(cqk, (kk2 & 1) ? vm : vp, r[kk2]);
            });
        });

        // ---- Levinson-Durbin (order 16) ----
        float A[ORDER];
        float E = r[0];
        #pragma unroll
        for (int ii = 1; ii <= ORDER; ++ii) {
            float acc = r[ii];
            #pragma unroll
            for (int j = 1; j < ii; ++j) acc += A[j - 1] * r[ii - j];
            const float kk = -__fdividef(acc, E);
            #pragma unroll
            for (int j = 0; j < (ii - 1) / 2; ++j) {
                const float tt = A[j];
                A[j]          = tt + kk * A[ii - 2 - j];
                A[ii - 2 - j] = A[ii - 2 - j] + kk * tt;
            }
            if (((ii - 1) & 1) == 1) {
                const int mid = (ii - 2) / 2;
                A[mid] = A[mid] + kk * A[mid];
            }
            A[ii - 1] = kk;
            E = E * (1.0f - kk * kk);
        }

        // ---- LPC -> cepstrum ----
        float cst[ORDER + 1];
        cst[0] = 0.5f * __logf(E);
        #pragma unroll
        for (int m = 1; m <= ORDER; ++m) {
            float acc = A[m - 1];
            #pragma unroll
            for (int k2 = 1; k2 < m; ++k2) {
                const float ratio = (float)k2 / (float)m;
                acc += ratio * cst[k2] * A[m - k2 - 1];
            }
            cst[m] = -acc;
        }

        // ---- lifter + store (warp writes 2KB contiguous) ----
        float o[ORDER];
        SF<0, ORDER>::run([&](auto icx) {
            constexpr int ii = icx.value;
            constexpr float lf = TB.lift[ii];
            o[ii] = cst[ii + 1] * lf;
        });

        const long long row = tile * RPW + lane;
        float4* o4 = reinterpret_cast<float4*>(out + row * 16);
        o4[0] = make_float4(o[0],  o[1],  o[2],  o[3]);
        o4[1] = make_float4(o[4],  o[5],  o[6],  o[7]);
        o4[2] = make_float4(o[8],  o[9],  o[10], o[11]);
        o4[3] = make_float4(o[12], o[13], o[14], o[15]);
    }
}

} // namespace plp

extern "C" void kernel_launch(void* const* d_in, const int* in_sizes, int n_in,
                              void* d_out, int out_size) {
    const float* x = (const float*)d_in[0];
    float* out = (float*)d_out;

    const int rows   = in_sizes[0] / plp::NBINS;   // 131072
    const int nTiles = rows / plp::RPW;            // 4096

    const int smem = plp::NBUF * plp::TILE_BYTES;  // 98688 B
    cudaFuncSetAttribute(plp::plp_kernel,
                         cudaFuncAttributeMaxDynamicSharedMemorySize, smem);
    int nSM = 0, dev = 0;
    cudaGetDevice(&dev);
    cudaDeviceGetAttribute(&nSM, cudaDevAttrMultiProcessorCount, dev);
    if (nSM <= 0) nSM = 148;

    int grid = plp::BLOCKS_PER_SM * nSM;           // 2 rings per SM
    if (grid > nTiles) grid = nTiles;

    plp::plp_kernel<<<grid, plp::BLOCK, smem>>>(x, out, nTiles);
}